// round 16
// baseline (speedup 1.0000x reference)
#include <cuda_runtime.h>
#include <cuda_fp16.h>
#include <cstdint>
#include <cstddef>

#define N_ROWS     131072
#define D_IN       512
#define D_H        1024
#define D_OUT      128
#define NUM_GROUPS 1024
#define LN_EPS     1e-5f

// ---------------- scratch (device globals: allocation-free rule) -------------
__device__ __half  g_bufA[(size_t)N_ROWS * D_H];       // layer inputs (fp16)
__device__ float   g_h  [(size_t)N_ROWS * D_H];        // fp32 hidden (512 MB)
__device__ float2  g_stats[(size_t)N_ROWS];            // per-row (mu, rs) of h2
__device__ float   g_mean[(size_t)NUM_GROUPS * D_H];   // 4 MB group means
__device__ __half  g_Bt1[(size_t)D_H * D_IN];          // W1^T fp16 [1024, 512]
__device__ __half  g_Bt2[(size_t)D_H * D_H];           // W2^T fp16 [1024, 1024]

// ======================= helpers ============================================
__device__ __forceinline__ uint32_t smem_u32(const void* p) {
    uint32_t a;
    asm("{ .reg .u64 t; cvta.to.shared.u64 t, %1; cvt.u32.u64 %0, t; }" : "=r"(a) : "l"(p));
    return a;
}
__device__ __forceinline__ uint32_t sw128(uint32_t b) { return b ^ ((b >> 3) & 0x70); }
__device__ __forceinline__ void cp_async16(uint32_t dst, const void* src) {
    asm volatile("cp.async.cg.shared.global [%0], [%1], 16;" :: "r"(dst), "l"(src) : "memory");
}
__device__ __forceinline__ void ldsm_x4(uint32_t* r, uint32_t addr) {
    asm volatile("ldmatrix.sync.aligned.m8n8.x4.shared.b16 {%0,%1,%2,%3}, [%4];"
                 : "=r"(r[0]), "=r"(r[1]), "=r"(r[2]), "=r"(r[3]) : "r"(addr));
}
__device__ __forceinline__ void mma_f16(float* c, const uint32_t* a, uint32_t b0, uint32_t b1) {
    asm volatile(
        "mma.sync.aligned.m16n8k16.row.col.f32.f16.f16.f32 "
        "{%0,%1,%2,%3}, {%4,%5,%6,%7}, {%8,%9}, {%0,%1,%2,%3};"
        : "+f"(c[0]), "+f"(c[1]), "+f"(c[2]), "+f"(c[3])
        : "r"(a[0]), "r"(a[1]), "r"(a[2]), "r"(a[3]), "r"(b0), "r"(b1));
}

// ======================= mma.sync plain fp16 GEMM ===========================
// C[M, Ncols] (fp32) = relu(A @ Bt^T + bias); A = [M, K] fp16, Bt = [N, K] fp16.
// 128x128 CTA, 8 warps 4(m)x2(n), 3 stages of [A 16K | B 16K], 2 CTAs/SM.
#define BM 128
#define BN 128
#define BK 64
#define STAGES 3
#define R_BYTES (BM * 128)                  // 16 KB per region
#define STAGE_BYTES (2 * R_BYTES)           // 32 KB

__global__ void __launch_bounds__(256, 2)
gemm_mma(const __half* __restrict__ A, const __half* __restrict__ Bt,
         const float* __restrict__ bias, float* __restrict__ C,
         int K, int Ncols)
{
    extern __shared__ __align__(1024) char smem[];
    const uint32_t sbase = smem_u32(smem);
    const int tid = threadIdx.x, lane = tid & 31, wid = tid >> 5;
    const int wm = wid & 3, wn = wid >> 2;                 // 4 x 2 warp grid
    const int m0 = blockIdx.y * BM, n0 = blockIdx.x * BN;
    const int NC = K / BK;

    auto fill = [&](int ci, int s) {
        const int kp = ci * BK;
        const uint32_t sA = sbase + s * STAGE_BYTES;
        const uint32_t sB = sA + R_BYTES;
#pragma unroll
        for (int j = 0; j < 4; j++) {
            const int c = tid + j * 256;
            const int r = c >> 3, col = (c & 7) * 16;
            cp_async16(sA + sw128(r * 128 + col),
                       (const char*)(A + (size_t)(m0 + r) * K + kp) + col);
        }
#pragma unroll
        for (int j = 0; j < 4; j++) {
            const int c = tid + j * 256;
            const int r = c >> 3, col = (c & 7) * 16;
            cp_async16(sB + sw128(r * 128 + col),
                       (const char*)(Bt + (size_t)(n0 + r) * K + kp) + col);
        }
        asm volatile("cp.async.commit_group;" ::: "memory");
    };

    float acc[2][8][4];
#pragma unroll
    for (int i = 0; i < 2; i++)
#pragma unroll
        for (int j = 0; j < 8; j++)
#pragma unroll
            for (int r = 0; r < 4; r++) acc[i][j][r] = 0.f;

    for (int j = 0; j < STAGES && j < NC; j++) fill(j, j);

    for (int i = 0; i < NC; i++) {
        const int s = i % STAGES;
        asm volatile("cp.async.wait_group %0;" :: "n"(STAGES - 1) : "memory");
        __syncthreads();
        const uint32_t sA = sbase + s * STAGE_BYTES;
        const uint32_t sB = sA + R_BYTES;

#pragma unroll
        for (int k16 = 0; k16 < BK / 16; k16++) {
            const uint32_t kb = k16 * 32 + (lane >> 4) * 16;
            uint32_t a[2][4];
#pragma unroll
            for (int mt = 0; mt < 2; mt++) {
                const int r = wm * 32 + mt * 16 + (lane & 15);
                ldsm_x4(a[mt], sA + sw128(r * 128 + kb));
            }
            uint32_t b[4][4];
#pragma unroll
            for (int nt2 = 0; nt2 < 4; nt2++) {
                const int r = wn * 64 + nt2 * 16 + (lane & 15);
                ldsm_x4(b[nt2], sB + sw128(r * 128 + kb));
            }
#pragma unroll
            for (int mt = 0; mt < 2; mt++)
#pragma unroll
                for (int nt = 0; nt < 8; nt++)
                    mma_f16(acc[mt][nt], a[mt], b[nt >> 1][nt & 1], b[nt >> 1][2 + (nt & 1)]);
        }
        __syncthreads();
        if (i + STAGES < NC) fill(i + STAGES, s);
        else asm volatile("cp.async.commit_group;" ::: "memory");
    }

    // epilogue: bias + relu, fp32 stores
#pragma unroll
    for (int mt = 0; mt < 2; mt++) {
#pragma unroll
        for (int nt = 0; nt < 8; nt++) {
            const int col = n0 + wn * 64 + nt * 8 + (lane & 3) * 2;
            const float b0 = bias[col], b1 = bias[col + 1];
            const int r0 = m0 + wm * 32 + mt * 16 + (lane >> 2);
            float v0 = fmaxf(acc[mt][nt][0] + b0, 0.f);
            float v1 = fmaxf(acc[mt][nt][1] + b1, 0.f);
            float v2 = fmaxf(acc[mt][nt][2] + b0, 0.f);
            float v3 = fmaxf(acc[mt][nt][3] + b1, 0.f);
            *(float2*)(C + (size_t)r0 * Ncols + col)       = make_float2(v0, v1);
            *(float2*)(C + (size_t)(r0 + 8) * Ncols + col) = make_float2(v2, v3);
        }
    }
}

// =================== operand prep kernels ===================================
// X [N, 512] f32 -> bufA [N, 512] plain fp16
__global__ void __launch_bounds__(256)
convertX(const float* __restrict__ X, __half* __restrict__ out)
{
    const size_t i4 = ((size_t)blockIdx.x * 256 + threadIdx.x) * 4;
    if (i4 >= (size_t)N_ROWS * D_IN) return;
    float4 v = *(const float4*)(X + i4);
    *(__half2*)(out + i4)     = __halves2half2(__float2half_rn(v.x), __float2half_rn(v.y));
    *(__half2*)(out + i4 + 2) = __halves2half2(__float2half_rn(v.z), __float2half_rn(v.w));
}

// W [K, Ncols] f32 -> Bt [Ncols, K] fp16 (rounded)
__global__ void __launch_bounds__(256)
convertW(const float* __restrict__ W, __half* __restrict__ Bt, int K, int Ncols)
{
    const size_t i = (size_t)blockIdx.x * 256 + threadIdx.x;
    if (i >= (size_t)K * Ncols) return;
    const int n = (int)(i % Ncols), k = (int)(i / Ncols);
    Bt[(size_t)n * K + k] = __float2half_rn(W[(size_t)k * Ncols + n]);
}

// LayerNorm(h fp32 [N,1024]) -> bufA [N,1024] plain fp16
__global__ void __launch_bounds__(256)
ln_convert(const float* __restrict__ H, const float* __restrict__ gamma,
           const float* __restrict__ beta, __half* __restrict__ out)
{
    const int row = blockIdx.x;
    const int t = threadIdx.x;
    float4 v = *(const float4*)(H + (size_t)row * D_H + t * 4);

    float s = v.x + v.y + v.z + v.w;
    float ss = v.x * v.x + v.y * v.y + v.z * v.z + v.w * v.w;
#pragma unroll
    for (int o = 16; o > 0; o >>= 1) {
        s  += __shfl_xor_sync(0xFFFFFFFFu, s,  o);
        ss += __shfl_xor_sync(0xFFFFFFFFu, ss, o);
    }
    __shared__ float ws[8], wss[8];
    const int w = t >> 5, l = t & 31;
    if (l == 0) { ws[w] = s; wss[w] = ss; }
    __syncthreads();
    if (w == 0) {
        s  = (l < 8) ? ws[l]  : 0.f;
        ss = (l < 8) ? wss[l] : 0.f;
#pragma unroll
        for (int o = 4; o > 0; o >>= 1) {
            s  += __shfl_xor_sync(0xFFFFFFFFu, s,  o);
            ss += __shfl_xor_sync(0xFFFFFFFFu, ss, o);
        }
        if (l == 0) { ws[0] = s; wss[0] = ss; }
    }
    __syncthreads();
    const float inv = 1.f / (float)D_H;
    const float mu  = ws[0] * inv;
    const float var = fmaxf(wss[0] * inv - mu * mu, 0.f);
    const float rs  = rsqrtf(var + LN_EPS);

    float4 gv = *(const float4*)(gamma + t * 4);
    float4 bv = *(const float4*)(beta  + t * 4);
    float n0 = (v.x - mu) * rs * gv.x + bv.x;
    float n1 = (v.y - mu) * rs * gv.y + bv.y;
    float n2 = (v.z - mu) * rs * gv.z + bv.z;
    float n3 = (v.w - mu) * rs * gv.w + bv.w;
    __half* oh = out + (size_t)row * D_H + t * 4;
    *(__half2*)(oh)     = __halves2half2(__float2half_rn(n0), __float2half_rn(n1));
    *(__half2*)(oh + 2) = __halves2half2(__float2half_rn(n2), __float2half_rn(n3));
}

// --------- per-row LN stats of h2 (fp32): warp per row ----------------------
__global__ void __launch_bounds__(256)
rowstats(const float* __restrict__ H, float2* __restrict__ stats)
{
    const int row = blockIdx.x * 8 + (threadIdx.x >> 5);
    const int lane = threadIdx.x & 31;
    const float* hr = H + (size_t)row * D_H;
    float s = 0.f, ss = 0.f;
#pragma unroll
    for (int q = 0; q < 8; q++) {            // 8 x float4 = 32 floats per lane
        float4 v = *(const float4*)(hr + q * 128 + lane * 4);
        s  += v.x + v.y + v.z + v.w;
        ss += v.x * v.x + v.y * v.y + v.z * v.z + v.w * v.w;
    }
#pragma unroll
    for (int o = 16; o > 0; o >>= 1) {
        s  += __shfl_xor_sync(0xFFFFFFFFu, s,  o);
        ss += __shfl_xor_sync(0xFFFFFFFFu, ss, o);
    }
    if (lane == 0) {
        const float inv = 1.f / (float)D_H;
        const float mu = s * inv;
        const float var = fmaxf(ss * inv - mu * mu, 0.f);
        stats[row] = make_float2(mu, rsqrtf(var + LN_EPS));
    }
}

// ======= deterministic segment mean of LN(h2) ===============================
// Two-scan shared index build (proven, no spill); gather is sync-free using
// precomputed (mu, rs). LN factored: mean_c = (S1_c - S0)/|g| * gamma_c + beta_c
// with S1_c = sum_r v_rc*rs_r, S0 = sum_r mu_r*rs_r.
// 256 threads, 4 cols/thread (one float4 per row).
#define SEG_CAP 4096
__global__ void __launch_bounds__(256)
segmean_ln(const float* __restrict__ H, const int* __restrict__ batch,
           const float2* __restrict__ stats,
           const float* __restrict__ gamma, const float* __restrict__ beta,
           float* __restrict__ mean)
{
    const int g = blockIdx.x;
    const int t = threadIdx.x;

    __shared__ int s_cnt[256];
    __shared__ int s_idx[SEG_CAP];
    __shared__ int s_total;

    int cnt = 0;
    for (int i = t; i < N_ROWS; i += 256)
        cnt += (batch[i] == g) ? 1 : 0;
    s_cnt[t] = cnt;
    __syncthreads();

    int off = 0;
    for (int u = 0; u < t; u++) off += s_cnt[u];
    if (t == 255) s_total = off + cnt;
    __syncthreads();
    const int total = s_total;

    int o = off;
    for (int i = t; i < N_ROWS; i += 256) {
        if (batch[i] == g) {
            if (o < SEG_CAP) s_idx[o] = i;
            o++;
        }
    }
    __syncthreads();

    float acc0 = 0.f, acc1 = 0.f, acc2 = 0.f, acc3 = 0.f, s0 = 0.f;

    const int m = total < SEG_CAP ? total : SEG_CAP;
    for (int j = 0; j < m; j++) {
        const int row = s_idx[j];
        const float2 st = stats[row];                  // broadcast load
        const float4 v = *(const float4*)(H + (size_t)row * D_H + t * 4);
        acc0 += v.x * st.y;
        acc1 += v.y * st.y;
        acc2 += v.z * st.y;
        acc3 += v.w * st.y;
        s0   += st.x * st.y;
    }

    const float inv = (total > 0) ? 1.f / (float)total : 0.f;
    float4 gv = *(const float4*)(gamma + t * 4);
    float4 bv = *(const float4*)(beta  + t * 4);
    float4 r;
    r.x = (acc0 - s0) * inv * gv.x + bv.x;
    r.y = (acc1 - s0) * inv * gv.y + bv.y;
    r.z = (acc2 - s0) * inv * gv.z + bv.z;
    r.w = (acc3 - s0) * inv * gv.w + bv.w;
    *(float4*)(mean + (size_t)g * D_H + t * 4) = r;
}

// --------- tiny fp32 GEMM: out[G,128] = mean[G,1024] @ W3[1024,128] + b3 ----
__global__ void __launch_bounds__(128)
minigemm(const float* __restrict__ mean, const float* __restrict__ W3,
         const float* __restrict__ b3, float* __restrict__ out)
{
    __shared__ float sm[8][D_H];            // 8 group rows, 32 KB
    const int g0 = blockIdx.x * 8;
    const int t = threadIdx.x;              // output column

    for (int i = t; i < 8 * D_H; i += 128)
        sm[i >> 10][i & 1023] = mean[(size_t)(g0 + (i >> 10)) * D_H + (i & 1023)];
    __syncthreads();

    float acc[8];
#pragma unroll
    for (int r = 0; r < 8; r++) acc[r] = 0.f;
    for (int k = 0; k < D_H; k++) {
        const float w = W3[(size_t)k * D_OUT + t];
#pragma unroll
        for (int r = 0; r < 8; r++) acc[r] += sm[r][k] * w;
    }
    const float bb = b3[t];
#pragma unroll
    for (int r = 0; r < 8; r++)
        out[(size_t)(g0 + r) * D_OUT + t] = acc[r] + bb;
}

// ---------------- launch -----------------------------------------------------
extern "C" void kernel_launch(void* const* d_in, const int* in_sizes, int n_in,
                              void* d_out, int out_size)
{
    const float* X   = (const float*)d_in[0];
    const float* W1  = (const float*)d_in[1];
    const float* b1  = (const float*)d_in[2];
    const float* g1  = (const float*)d_in[3];
    const float* be1 = (const float*)d_in[4];
    const float* W2  = (const float*)d_in[5];
    const float* b2  = (const float*)d_in[6];
    const float* g2  = (const float*)d_in[7];
    const float* be2 = (const float*)d_in[8];
    const float* W3  = (const float*)d_in[9];
    const float* b3  = (const float*)d_in[10];
    const int*   ab  = (const int*)d_in[11];
    float* out = (float*)d_out;

    __half *bufA, *Bt1, *Bt2;
    float *h, *mean;
    float2* stats;
    cudaGetSymbolAddress((void**)&bufA,  g_bufA);
    cudaGetSymbolAddress((void**)&h,     g_h);
    cudaGetSymbolAddress((void**)&stats, g_stats);
    cudaGetSymbolAddress((void**)&mean,  g_mean);
    cudaGetSymbolAddress((void**)&Bt1,   g_Bt1);
    cudaGetSymbolAddress((void**)&Bt2,   g_Bt2);

    const int SMEM = STAGES * STAGE_BYTES;   // 96 KB
    static bool attr_set = false;
    if (!attr_set) {
        cudaFuncSetAttribute(gemm_mma, cudaFuncAttributeMaxDynamicSharedMemorySize, SMEM);
        attr_set = true;
    }

    // operand prep
    convertW<<<(D_IN * D_H + 255) / 256, 256>>>(W1, Bt1, D_IN, D_H);
    convertW<<<(D_H * D_H + 255) / 256, 256>>>(W2, Bt2, D_H, D_H);
    convertX<<<(int)(((size_t)N_ROWS * D_IN / 4 + 255) / 256), 256>>>(X, bufA);

    // layer 1: fp16 [N,512] @ [512,1024] -> h (fp32)
    gemm_mma<<<dim3(D_H / BN, N_ROWS / BM), 256, SMEM>>>(
        bufA, Bt1, b1, h, D_IN, D_H);
    ln_convert<<<N_ROWS, 256>>>(h, g1, be1, bufA);

    // layer 2: fp16 [N,1024] @ [1024,1024] -> h (fp32, raw pre-LN)
    gemm_mma<<<dim3(D_H / BN, N_ROWS / BM), 256, SMEM>>>(
        bufA, Bt2, b2, h, D_H, D_H);

    // LN2 stats, syncless fused LN2+group-mean, layer 3 via linearity
    rowstats<<<N_ROWS / 8, 256>>>(h, stats);
    segmean_ln<<<NUM_GROUPS, 256>>>(h, ab, stats, g2, be2, mean);
    minigemm<<<NUM_GROUPS / 8, 128>>>(mean, W3, b3, out);
}

// round 17
// speedup vs baseline: 1.0553x; 1.0553x over previous
#include <cuda_runtime.h>
#include <cuda_fp16.h>
#include <cstdint>
#include <cstddef>

#define N_ROWS     131072
#define D_IN       512
#define D_H        1024
#define D_OUT      128
#define NUM_GROUPS 1024
#define LN_EPS     1e-5f
#define NXB        (D_H / 64)               // 64-col stat blocks per row (16)

// ---------------- scratch (device globals: allocation-free rule) -------------
__device__ __half  g_bufA[(size_t)N_ROWS * D_H];       // layer inputs (fp16)
__device__ float   g_h  [(size_t)N_ROWS * D_H];        // fp32 hidden (512 MB)
__device__ float2  g_part[(size_t)N_ROWS * NXB];       // per-row stat partials (16 MB)
__device__ float2  g_stats[(size_t)N_ROWS];            // per-row (mu, rs)
__device__ float   g_mean[(size_t)NUM_GROUPS * D_H];   // 4 MB group means
__device__ __half  g_Bt1[(size_t)D_H * D_IN];          // W1^T fp16 [1024, 512]
__device__ __half  g_Bt2[(size_t)D_H * D_H];           // W2^T fp16 [1024, 1024]

// ======================= helpers ============================================
__device__ __forceinline__ uint32_t smem_u32(const void* p) {
    uint32_t a;
    asm("{ .reg .u64 t; cvta.to.shared.u64 t, %1; cvt.u32.u64 %0, t; }" : "=r"(a) : "l"(p));
    return a;
}
__device__ __forceinline__ uint32_t sw128(uint32_t b) { return b ^ ((b >> 3) & 0x70); }
__device__ __forceinline__ void cp_async16(uint32_t dst, const void* src) {
    asm volatile("cp.async.cg.shared.global [%0], [%1], 16;" :: "r"(dst), "l"(src) : "memory");
}
__device__ __forceinline__ void ldsm_x4(uint32_t* r, uint32_t addr) {
    asm volatile("ldmatrix.sync.aligned.m8n8.x4.shared.b16 {%0,%1,%2,%3}, [%4];"
                 : "=r"(r[0]), "=r"(r[1]), "=r"(r[2]), "=r"(r[3]) : "r"(addr));
}
__device__ __forceinline__ void mma_f16(float* c, const uint32_t* a, uint32_t b0, uint32_t b1) {
    asm volatile(
        "mma.sync.aligned.m16n8k16.row.col.f32.f16.f16.f32 "
        "{%0,%1,%2,%3}, {%4,%5,%6,%7}, {%8,%9}, {%0,%1,%2,%3};"
        : "+f"(c[0]), "+f"(c[1]), "+f"(c[2]), "+f"(c[3])
        : "r"(a[0]), "r"(a[1]), "r"(a[2]), "r"(a[3]), "r"(b0), "r"(b1));
}

// ======================= mma.sync plain fp16 GEMM ===========================
// C[M, Ncols] (fp32) = relu(A @ Bt^T + bias); A = [M, K] fp16, Bt = [N, K] fp16.
// Epilogue additionally emits per-(row, 64-col-block) stat partials (sum, sumsq)
// into part[row * NXB + xb]. 128x128 CTA, 8 warps 4(m)x2(n), 3 stages, 2 CTA/SM.
#define BM 128
#define BN 128
#define BK 64
#define STAGES 3
#define R_BYTES (BM * 128)                  // 16 KB per region
#define STAGE_BYTES (2 * R_BYTES)           // 32 KB

__global__ void __launch_bounds__(256, 2)
gemm_mma(const __half* __restrict__ A, const __half* __restrict__ Bt,
         const float* __restrict__ bias, float* __restrict__ C,
         float2* __restrict__ part, int K, int Ncols)
{
    extern __shared__ __align__(1024) char smem[];
    const uint32_t sbase = smem_u32(smem);
    const int tid = threadIdx.x, lane = tid & 31, wid = tid >> 5;
    const int wm = wid & 3, wn = wid >> 2;                 // 4 x 2 warp grid
    const int m0 = blockIdx.y * BM, n0 = blockIdx.x * BN;
    const int NC = K / BK;

    auto fill = [&](int ci, int s) {
        const int kp = ci * BK;
        const uint32_t sA = sbase + s * STAGE_BYTES;
        const uint32_t sB = sA + R_BYTES;
#pragma unroll
        for (int j = 0; j < 4; j++) {
            const int c = tid + j * 256;
            const int r = c >> 3, col = (c & 7) * 16;
            cp_async16(sA + sw128(r * 128 + col),
                       (const char*)(A + (size_t)(m0 + r) * K + kp) + col);
        }
#pragma unroll
        for (int j = 0; j < 4; j++) {
            const int c = tid + j * 256;
            const int r = c >> 3, col = (c & 7) * 16;
            cp_async16(sB + sw128(r * 128 + col),
                       (const char*)(Bt + (size_t)(n0 + r) * K + kp) + col);
        }
        asm volatile("cp.async.commit_group;" ::: "memory");
    };

    float acc[2][8][4];
#pragma unroll
    for (int i = 0; i < 2; i++)
#pragma unroll
        for (int j = 0; j < 8; j++)
#pragma unroll
            for (int r = 0; r < 4; r++) acc[i][j][r] = 0.f;

    for (int j = 0; j < STAGES && j < NC; j++) fill(j, j);

    for (int i = 0; i < NC; i++) {
        const int s = i % STAGES;
        asm volatile("cp.async.wait_group %0;" :: "n"(STAGES - 1) : "memory");
        __syncthreads();
        const uint32_t sA = sbase + s * STAGE_BYTES;
        const uint32_t sB = sA + R_BYTES;

#pragma unroll
        for (int k16 = 0; k16 < BK / 16; k16++) {
            const uint32_t kb = k16 * 32 + (lane >> 4) * 16;
            uint32_t a[2][4];
#pragma unroll
            for (int mt = 0; mt < 2; mt++) {
                const int r = wm * 32 + mt * 16 + (lane & 15);
                ldsm_x4(a[mt], sA + sw128(r * 128 + kb));
            }
            uint32_t b[4][4];
#pragma unroll
            for (int nt2 = 0; nt2 < 4; nt2++) {
                const int r = wn * 64 + nt2 * 16 + (lane & 15);
                ldsm_x4(b[nt2], sB + sw128(r * 128 + kb));
            }
#pragma unroll
            for (int mt = 0; mt < 2; mt++)
#pragma unroll
                for (int nt = 0; nt < 8; nt++)
                    mma_f16(acc[mt][nt], a[mt], b[nt >> 1][nt & 1], b[nt >> 1][2 + (nt & 1)]);
        }
        __syncthreads();
        if (i + STAGES < NC) fill(i + STAGES, s);
        else asm volatile("cp.async.commit_group;" ::: "memory");
    }

    // epilogue: bias + relu, fp32 stores, + per-row stat partials
    const int xb = (n0 >> 6) + wn;          // 64-col block index within row
#pragma unroll
    for (int mt = 0; mt < 2; mt++) {
        float sa = 0.f, qa = 0.f, sb = 0.f, qb = 0.f;
        const int r0 = m0 + wm * 32 + mt * 16 + (lane >> 2);
#pragma unroll
        for (int nt = 0; nt < 8; nt++) {
            const int col = n0 + wn * 64 + nt * 8 + (lane & 3) * 2;
            const float b0 = bias[col], b1 = bias[col + 1];
            float v0 = fmaxf(acc[mt][nt][0] + b0, 0.f);
            float v1 = fmaxf(acc[mt][nt][1] + b1, 0.f);
            float v2 = fmaxf(acc[mt][nt][2] + b0, 0.f);
            float v3 = fmaxf(acc[mt][nt][3] + b1, 0.f);
            sa += v0 + v1; qa += v0 * v0 + v1 * v1;
            sb += v2 + v3; qb += v2 * v2 + v3 * v3;
            *(float2*)(C + (size_t)r0 * Ncols + col)       = make_float2(v0, v1);
            *(float2*)(C + (size_t)(r0 + 8) * Ncols + col) = make_float2(v2, v3);
        }
        // quad reduce (lanes differing in lane&3 share the row)
#pragma unroll
        for (int o = 1; o < 4; o <<= 1) {
            sa += __shfl_xor_sync(0xFFFFFFFFu, sa, o);
            qa += __shfl_xor_sync(0xFFFFFFFFu, qa, o);
            sb += __shfl_xor_sync(0xFFFFFFFFu, sb, o);
            qb += __shfl_xor_sync(0xFFFFFFFFu, qb, o);
        }
        if ((lane & 3) == 0) {
            part[(size_t)r0 * NXB + xb]       = make_float2(sa, qa);
            part[(size_t)(r0 + 8) * NXB + xb] = make_float2(sb, qb);
        }
    }
}

// =================== operand prep kernels ===================================
// X [N, 512] f32 -> bufA [N, 512] plain fp16
__global__ void __launch_bounds__(256)
convertX(const float* __restrict__ X, __half* __restrict__ out)
{
    const size_t i4 = ((size_t)blockIdx.x * 256 + threadIdx.x) * 4;
    if (i4 >= (size_t)N_ROWS * D_IN) return;
    float4 v = *(const float4*)(X + i4);
    *(__half2*)(out + i4)     = __halves2half2(__float2half_rn(v.x), __float2half_rn(v.y));
    *(__half2*)(out + i4 + 2) = __halves2half2(__float2half_rn(v.z), __float2half_rn(v.w));
}

// W [K, Ncols] f32 -> Bt [Ncols, K] fp16 (rounded)
__global__ void __launch_bounds__(256)
convertW(const float* __restrict__ W, __half* __restrict__ Bt, int K, int Ncols)
{
    const size_t i = (size_t)blockIdx.x * 256 + threadIdx.x;
    if (i >= (size_t)K * Ncols) return;
    const int n = (int)(i % Ncols), k = (int)(i / Ncols);
    Bt[(size_t)n * K + k] = __float2half_rn(W[(size_t)k * Ncols + n]);
}

// --------- fold stat partials -> per-row (mu, rs) ---------------------------
__global__ void __launch_bounds__(256)
reduce_stats(const float2* __restrict__ part, float2* __restrict__ stats)
{
    const int row = blockIdx.x * 256 + threadIdx.x;
    if (row >= N_ROWS) return;
    const float2* p = part + (size_t)row * NXB;
    float s = 0.f, ss = 0.f;
#pragma unroll
    for (int i = 0; i < NXB; i++) { s += p[i].x; ss += p[i].y; }
    const float inv = 1.f / (float)D_H;
    const float mu = s * inv;
    const float var = fmaxf(ss * inv - mu * mu, 0.f);
    stats[row] = make_float2(mu, rsqrtf(var + LN_EPS));
}

// LN(h; stats) -> bufA fp16. Pure streaming, no reductions.
__global__ void __launch_bounds__(256)
ln_convert_ns(const float* __restrict__ H, const float2* __restrict__ stats,
              const float* __restrict__ gamma, const float* __restrict__ beta,
              __half* __restrict__ out)
{
    const size_t i4 = ((size_t)blockIdx.x * 256 + threadIdx.x) * 4;
    if (i4 >= (size_t)N_ROWS * D_H) return;
    const int row = (int)(i4 >> 10);
    const int col = (int)(i4 & (D_H - 1));
    const float2 st = stats[row];
    float4 v = *(const float4*)(H + i4);
    float4 gv = *(const float4*)(gamma + col);
    float4 bv = *(const float4*)(beta + col);
    float n0 = (v.x - st.x) * st.y * gv.x + bv.x;
    float n1 = (v.y - st.x) * st.y * gv.y + bv.y;
    float n2 = (v.z - st.x) * st.y * gv.z + bv.z;
    float n3 = (v.w - st.x) * st.y * gv.w + bv.w;
    *(__half2*)(out + i4)     = __halves2half2(__float2half_rn(n0), __float2half_rn(n1));
    *(__half2*)(out + i4 + 2) = __halves2half2(__float2half_rn(n2), __float2half_rn(n3));
}

// ======= deterministic segment mean of LN(h2), sync-free gather =============
// mean_c = (S1_c - S0)/|g| * gamma_c + beta_c,  S1_c = sum_r v_rc*rs_r,
// S0 = sum_r mu_r*rs_r. 256 threads, 4 cols/thread (one float4 per row).
#define SEG_CAP 4096
__global__ void __launch_bounds__(256)
segmean_ln(const float* __restrict__ H, const int* __restrict__ batch,
           const float2* __restrict__ stats,
           const float* __restrict__ gamma, const float* __restrict__ beta,
           float* __restrict__ mean)
{
    const int g = blockIdx.x;
    const int t = threadIdx.x;

    __shared__ int s_cnt[256];
    __shared__ int s_idx[SEG_CAP];
    __shared__ int s_total;

    int cnt = 0;
    for (int i = t; i < N_ROWS; i += 256)
        cnt += (batch[i] == g) ? 1 : 0;
    s_cnt[t] = cnt;
    __syncthreads();

    int off = 0;
    for (int u = 0; u < t; u++) off += s_cnt[u];
    if (t == 255) s_total = off + cnt;
    __syncthreads();
    const int total = s_total;

    int o = off;
    for (int i = t; i < N_ROWS; i += 256) {
        if (batch[i] == g) {
            if (o < SEG_CAP) s_idx[o] = i;
            o++;
        }
    }
    __syncthreads();

    float acc0 = 0.f, acc1 = 0.f, acc2 = 0.f, acc3 = 0.f, s0 = 0.f;

    const int m = total < SEG_CAP ? total : SEG_CAP;
    for (int j = 0; j < m; j++) {
        const int row = s_idx[j];
        const float2 st = stats[row];                  // broadcast load
        const float4 v = *(const float4*)(H + (size_t)row * D_H + t * 4);
        acc0 += v.x * st.y;
        acc1 += v.y * st.y;
        acc2 += v.z * st.y;
        acc3 += v.w * st.y;
        s0   += st.x * st.y;
    }

    const float inv = (total > 0) ? 1.f / (float)total : 0.f;
    float4 gv = *(const float4*)(gamma + t * 4);
    float4 bv = *(const float4*)(beta  + t * 4);
    float4 r;
    r.x = (acc0 - s0) * inv * gv.x + bv.x;
    r.y = (acc1 - s0) * inv * gv.y + bv.y;
    r.z = (acc2 - s0) * inv * gv.z + bv.z;
    r.w = (acc3 - s0) * inv * gv.w + bv.w;
    *(float4*)(mean + (size_t)g * D_H + t * 4) = r;
}

// --------- tiny fp32 GEMM: out[G,128] = mean[G,1024] @ W3[1024,128] + b3 ----
__global__ void __launch_bounds__(128)
minigemm(const float* __restrict__ mean, const float* __restrict__ W3,
         const float* __restrict__ b3, float* __restrict__ out)
{
    __shared__ float sm[8][D_H];            // 8 group rows, 32 KB
    const int g0 = blockIdx.x * 8;
    const int t = threadIdx.x;              // output column

    for (int i = t; i < 8 * D_H; i += 128)
        sm[i >> 10][i & 1023] = mean[(size_t)(g0 + (i >> 10)) * D_H + (i & 1023)];
    __syncthreads();

    float acc[8];
#pragma unroll
    for (int r = 0; r < 8; r++) acc[r] = 0.f;
    for (int k = 0; k < D_H; k++) {
        const float w = W3[(size_t)k * D_OUT + t];
#pragma unroll
        for (int r = 0; r < 8; r++) acc[r] += sm[r][k] * w;
    }
    const float bb = b3[t];
#pragma unroll
    for (int r = 0; r < 8; r++)
        out[(size_t)(g0 + r) * D_OUT + t] = acc[r] + bb;
}

// ---------------- launch -----------------------------------------------------
extern "C" void kernel_launch(void* const* d_in, const int* in_sizes, int n_in,
                              void* d_out, int out_size)
{
    const float* X   = (const float*)d_in[0];
    const float* W1  = (const float*)d_in[1];
    const float* b1  = (const float*)d_in[2];
    const float* g1  = (const float*)d_in[3];
    const float* be1 = (const float*)d_in[4];
    const float* W2  = (const float*)d_in[5];
    const float* b2  = (const float*)d_in[6];
    const float* g2  = (const float*)d_in[7];
    const float* be2 = (const float*)d_in[8];
    const float* W3  = (const float*)d_in[9];
    const float* b3  = (const float*)d_in[10];
    const int*   ab  = (const int*)d_in[11];
    float* out = (float*)d_out;

    __half *bufA, *Bt1, *Bt2;
    float *h, *mean;
    float2 *part, *stats;
    cudaGetSymbolAddress((void**)&bufA,  g_bufA);
    cudaGetSymbolAddress((void**)&h,     g_h);
    cudaGetSymbolAddress((void**)&part,  g_part);
    cudaGetSymbolAddress((void**)&stats, g_stats);
    cudaGetSymbolAddress((void**)&mean,  g_mean);
    cudaGetSymbolAddress((void**)&Bt1,   g_Bt1);
    cudaGetSymbolAddress((void**)&Bt2,   g_Bt2);

    const int SMEM = STAGES * STAGE_BYTES;   // 96 KB
    static bool attr_set = false;
    if (!attr_set) {
        cudaFuncSetAttribute(gemm_mma, cudaFuncAttributeMaxDynamicSharedMemorySize, SMEM);
        attr_set = true;
    }

    // operand prep
    convertW<<<(D_IN * D_H + 255) / 256, 256>>>(W1, Bt1, D_IN, D_H);
    convertW<<<(D_H * D_H + 255) / 256, 256>>>(W2, Bt2, D_H, D_H);
    convertX<<<(int)(((size_t)N_ROWS * D_IN / 4 + 255) / 256), 256>>>(X, bufA);

    const int LN_GRID = (int)(((size_t)N_ROWS * D_H / 4 + 255) / 256);

    // layer 1: fp16 GEMM -> h (fp32) + stat partials; fold; stream LN1
    gemm_mma<<<dim3(D_H / BN, N_ROWS / BM), 256, SMEM>>>(
        bufA, Bt1, b1, h, part, D_IN, D_H);
    reduce_stats<<<N_ROWS / 256, 256>>>(part, stats);
    ln_convert_ns<<<LN_GRID, 256>>>(h, stats, g1, be1, bufA);

    // layer 2: fp16 GEMM -> h (fp32) + stat partials; fold
    gemm_mma<<<dim3(D_H / BN, N_ROWS / BM), 256, SMEM>>>(
        bufA, Bt2, b2, h, part, D_H, D_H);
    reduce_stats<<<N_ROWS / 256, 256>>>(part, stats);

    // syncless fused LN2 + per-group mean, layer 3 via linearity
    segmean_ln<<<NUM_GROUPS, 256>>>(h, ab, stats, g2, be2, mean);
    minigemm<<<NUM_GROUPS / 8, 128>>>(mean, W3, b3, out);
}